// round 13
// baseline (speedup 1.0000x reference)
#include <cuda_runtime.h>
#include <string.h>

#define NN 512
#define H  64
#define ED 6
#define NL 4
#define EE (NN*NN)
#define LN_EPS 1e-5f
#define NDST 16        // dsts per node block
#define DP 20          // padded dst stride for node smem arrays

// Scratch (device globals: no allocations allowed)
__device__ float g_h  [NN*H];
__device__ float g_Hd [NN*H];         // dst-side attention proj (+att_b1), row-major
__device__ float g_HsT[2][H*NN];      // src-side attention proj, DIM-MAJOR [j][s], double buffered
__device__ float g_Av [2][NN*H];      // src-side value proj (+val_b1), row-major, double buffered
__device__ float g_eaT[ED*EE];        // edge_attr transposed: eaT[k][d][s]
__device__ float g_pm  [2*NN];        // per (2d+half) softmax partial max
__device__ float g_ps  [2*NN];        // per (2d+half) softmax partial sum
__device__ float g_pacc[2*NN*H];      // per (2d+half) weighted value partial

__device__ __forceinline__ float warp_sum(float v) {
#pragma unroll
    for (int o = 16; o; o >>= 1) v += __shfl_xor_sync(0xffffffffu, v, o);
    return v;
}
__device__ __forceinline__ float warp_max(float v) {
#pragma unroll
    for (int o = 16; o; o >>= 1) v = fmaxf(v, __shfl_xor_sync(0xffffffffu, v, o));
    return v;
}

// Packed fp32x2 ops (sm_103a): 2 fp32 FMAs per instruction
__device__ __forceinline__ float2 ffma2(float2 a, float2 b, float2 c) {
    unsigned long long ua, ub, uc, ur;
    memcpy(&ua, &a, 8); memcpy(&ub, &b, 8); memcpy(&uc, &c, 8);
    asm("fma.rn.f32x2 %0, %1, %2, %3;" : "=l"(ur) : "l"(ua), "l"(ub), "l"(uc));
    float2 r; memcpy(&r, &ur, 8); return r;
}
__device__ __forceinline__ float2 fadd2(float2 a, float2 b) {
    unsigned long long ua, ub, ur;
    memcpy(&ua, &a, 8); memcpy(&ub, &b, 8);
    asm("add.rn.f32x2 %0, %1, %2;" : "=l"(ur) : "l"(ua), "l"(ub));
    float2 r; memcpy(&r, &ur, 8); return r;
}
__device__ __forceinline__ float2 fmul2(float2 a, float2 b) {
    unsigned long long ua, ub, ur;
    memcpy(&ua, &a, 8); memcpy(&ub, &b, 8);
    asm("mul.rn.f32x2 %0, %1, %2;" : "=l"(ur) : "l"(ua), "l"(ub));
    float2 r; memcpy(&r, &ur, 8); return r;
}

// Per-node tables: Hd = h@Wa[0:64]+b1a (row), HsT = h@Wa[64:128] (dim-major), Av = h@Wv[0:64]+b1v (row)
__device__ __forceinline__ void compute_tables(
    int d, int t, int wb, const float* h_sh,
    const float* __restrict__ attW1, const float* __restrict__ attB1,
    const float* __restrict__ valW1, const float* __restrict__ valB1)
{
    float ad = attB1[t], as = 0.f, av = valB1[t];
#pragma unroll 8
    for (int k = 0; k < H; k++) {
        float hk = h_sh[k];
        ad += hk * attW1[k * H + t];
        as += hk * attW1[(H + k) * H + t];
        av += hk * valW1[k * H + t];
    }
    g_Hd[d * H + t]       = ad;
    g_HsT[wb][t * NN + d] = as;
    g_Av[wb][d * H + t]   = av;
}

// Transpose edge_attr: ea[s][d][k] -> eaT[k][d][s]. grid (16,16), block 256.
__global__ void __launch_bounds__(256) ea_transpose_kernel(const float* __restrict__ ea)
{
    __shared__ float t_sh[ED][32][33];
    const int t = threadIdx.x, w = t >> 5, lane = t & 31;
    const int bs = blockIdx.x * 32, bd = blockIdx.y * 32;

#pragma unroll
    for (int rr = 0; rr < 4; rr++) {
        int s_loc = w + rr * 8;
        const float* base = ea + ((size_t)(bs + s_loc) * NN + bd) * ED + lane * ED;
        float2 v0 = *(const float2*)(base);
        float2 v1 = *(const float2*)(base + 2);
        float2 v2 = *(const float2*)(base + 4);
        t_sh[0][lane][s_loc] = v0.x; t_sh[1][lane][s_loc] = v0.y;
        t_sh[2][lane][s_loc] = v1.x; t_sh[3][lane][s_loc] = v1.y;
        t_sh[4][lane][s_loc] = v2.x; t_sh[5][lane][s_loc] = v2.y;
    }
    __syncthreads();
#pragma unroll
    for (int idx = t; idx < ED * 32 * 32; idx += 256) {
        int k = idx >> 10, r = idx & 1023, dl = r >> 5, sl = r & 31;
        g_eaT[(size_t)k * EE + (size_t)(bd + dl) * NN + bs + sl] = t_sh[k][dl][sl];
    }
}

// Encoder: h = relu(x@W1+b1)@W2+b2, then layer-0 tables (buffer 0). grid=512, block=64
__global__ void __launch_bounds__(H) enc_kernel(
    const float* __restrict__ x,
    const float* __restrict__ ew1, const float* __restrict__ eb1,
    const float* __restrict__ ew2, const float* __restrict__ eb2,
    const float* __restrict__ attW1, const float* __restrict__ attB1,
    const float* __restrict__ valW1, const float* __restrict__ valB1)
{
    int d = blockIdx.x, t = threadIdx.x;
    __shared__ float xs[ED], hid[H], hsn[H];
    if (t < ED) xs[t] = x[d * ED + t];
    __syncthreads();
    float a = eb1[t];
#pragma unroll
    for (int k = 0; k < ED; k++) a += xs[k] * ew1[k * H + t];
    hid[t] = fmaxf(a, 0.f);
    __syncthreads();
    float hv = eb2[t];
#pragma unroll 8
    for (int k = 0; k < H; k++) hv += hid[k] * ew2[k * H + t];
    g_h[d * H + t] = hv;
    hsn[t] = hv;
    __syncthreads();
    compute_tables(d, t, 0, hsn, attW1, attB1, valW1, valB1);
}

// Edge kernel (proven R8 structure): grid 1024 = 2 blocks per dst (half=bid&1,
// 256 srcs each), 128 threads = 4 warps; warp w owns local srcs [w*64,+64);
// lane owns the pair (2*lane, 2*lane+1). Pre-dup f32x2 smem operands, per-warp
// register softmax, block combine; partial (m,s,acc[64]) per (2d+half) to global.
__global__ void __launch_bounds__(128, 7) edge_kernel(
    const float* __restrict__ attW1e,   // [6,64] edge rows of att_w1[l]
    const float* __restrict__ attW2,    // [64]
    const float* __restrict__ valW1e,   // [6,64] edge rows of val_w1[l]
    int rb)
{
    const int bid = blockIdx.x;
    const int d = bid >> 1, half = bid & 1;
    const int t = threadIdx.x, w = t >> 5, lane = t & 31;

    __shared__ __align__(16) float4 wa4[H * 4];
    __shared__ __align__(16) float4 ea2[256 * 3];
    __shared__ __align__(16) float2 wexp2[256];
    __shared__ float pm[4], ps[4], pacc[4 * H];

    if (t < H) {
        int j = t;
        float w0 = attW1e[0 * H + j], w1 = attW1e[1 * H + j];
        float w2 = attW1e[2 * H + j], w3 = attW1e[3 * H + j];
        float w4 = attW1e[4 * H + j], w5 = attW1e[5 * H + j];
        float wo = attW2[j];
        float hd = g_Hd[d * H + j];
        wa4[j * 4 + 0] = make_float4(w0, w0, w1, w1);
        wa4[j * 4 + 1] = make_float4(w2, w2, w3, w3);
        wa4[j * 4 + 2] = make_float4(w4, w4, w5, w5);
        wa4[j * 4 + 3] = make_float4(wo, wo, hd, hd);
    }

    const float* HsT = g_HsT[rb];
    const float* AvL = g_Av[rb];
    const int sl = w * 64 + 2 * lane;
    const int sg = half * 256 + sl;

    float2 eav[ED];
#pragma unroll
    for (int k = 0; k < ED; k++)
        eav[k] = *(const float2*)(g_eaT + (size_t)k * EE + d * NN + sg);

    ea2[(sl + 0) * 3 + 0] = make_float4(eav[0].x, eav[0].x, eav[1].x, eav[1].x);
    ea2[(sl + 0) * 3 + 1] = make_float4(eav[2].x, eav[2].x, eav[3].x, eav[3].x);
    ea2[(sl + 0) * 3 + 2] = make_float4(eav[4].x, eav[4].x, eav[5].x, eav[5].x);
    ea2[(sl + 1) * 3 + 0] = make_float4(eav[0].y, eav[0].y, eav[1].y, eav[1].y);
    ea2[(sl + 1) * 3 + 1] = make_float4(eav[2].y, eav[2].y, eav[3].y, eav[3].y);
    ea2[(sl + 1) * 3 + 2] = make_float4(eav[4].y, eav[4].y, eav[5].y, eav[5].y);
    __syncthreads();

    // ---- Pass 1: attention logits for the 2 srcs, full j-loop ----
    float2 lg = make_float2(0.f, 0.f);
    const float2 c02 = make_float2(0.2f, 0.2f);
#pragma unroll 8
    for (int j = 0; j < H; j++) {
        float4 c0 = wa4[j * 4 + 0];
        float4 c1 = wa4[j * 4 + 1];
        float4 c2 = wa4[j * 4 + 2];
        float4 c3 = wa4[j * 4 + 3];
        float2 hs2 = *(const float2*)(HsT + j * NN + sg);
        float2 z  = fadd2(hs2, make_float2(c3.z, c3.w));
        float2 z2 = fmul2(eav[3], make_float2(c1.z, c1.w));
        z  = ffma2(eav[0], make_float2(c0.x, c0.y), z);
        z2 = ffma2(eav[4], make_float2(c2.x, c2.y), z2);
        z  = ffma2(eav[1], make_float2(c0.z, c0.w), z);
        z2 = ffma2(eav[5], make_float2(c2.z, c2.w), z2);
        z  = ffma2(eav[2], make_float2(c1.x, c1.y), z);
        z  = fadd2(z, z2);
        float2 s = fmul2(z, c02);
        z.x = fmaxf(z.x, s.x);
        z.y = fmaxf(z.y, s.y);
        lg = ffma2(z, make_float2(c3.x, c3.y), lg);
    }

    // ---- Per-warp register softmax over this warp's 64 srcs ----
    {
        float m = warp_max(fmaxf(lg.x, lg.y));
        float e0 = __expf(lg.x - m), e1 = __expf(lg.y - m);
        float s_w = warp_sum(e0 + e1);
        if (lane == 0) { pm[w] = m; ps[w] = s_w; }
        *(float4*)(wexp2 + sl) = make_float4(e0, e0, e1, e1);
    }
    __syncthreads();

    // ---- Pass 2: alpha-weighted value aggregation (f32x2, 2 dims/lane) ----
    const int j0 = 2 * lane;
    float2 wv[ED];
#pragma unroll
    for (int k = 0; k < ED; k++) wv[k] = *(const float2*)(valW1e + k * H + j0);

    float2 acc0 = make_float2(0.f, 0.f), acc1 = make_float2(0.f, 0.f);
    const int base = w * 64;
    const float* avbase = AvL + (size_t)(half * 256) * H + j0;
#pragma unroll 4
    for (int i = 0; i < 64; i += 2) {
#pragma unroll
        for (int u = 0; u < 2; u++) {
            int s = base + i + u;
            float4 q0 = ea2[s * 3 + 0];
            float4 q1 = ea2[s * 3 + 1];
            float4 q2 = ea2[s * 3 + 2];
            float2 p = *(const float2*)(avbase + (size_t)s * H);
            p = ffma2(make_float2(q0.x, q0.y), wv[0], p);
            p = ffma2(make_float2(q0.z, q0.w), wv[1], p);
            p = ffma2(make_float2(q1.x, q1.y), wv[2], p);
            p = ffma2(make_float2(q1.z, q1.w), wv[3], p);
            p = ffma2(make_float2(q2.x, q2.y), wv[4], p);
            p = ffma2(make_float2(q2.z, q2.w), wv[5], p);
            p.x = fmaxf(p.x, 0.f);
            p.y = fmaxf(p.y, 0.f);
            float2 wt2 = wexp2[s];
            if (u) acc1 = ffma2(wt2, p, acc1);
            else   acc0 = ffma2(wt2, p, acc0);
        }
    }
    acc0 = fadd2(acc0, acc1);
    *(float2*)(pacc + w * H + j0) = acc0;
    __syncthreads();

    // ---- Block combine 4 warp partials, write global partial ----
    if (t < H) {
        float M = fmaxf(fmaxf(pm[0], pm[1]), fmaxf(pm[2], pm[3]));
        float sc0 = __expf(pm[0] - M), sc1 = __expf(pm[1] - M);
        float sc2 = __expf(pm[2] - M), sc3 = __expf(pm[3] - M);
        float stot = ps[0] * sc0 + ps[1] * sc1 + ps[2] * sc2 + ps[3] * sc3;
        float a = pacc[0 * H + t] * sc0 + pacc[1 * H + t] * sc1
                + pacc[2 * H + t] * sc2 + pacc[3 * H + t] * sc3;
        g_pacc[bid * H + t] = a;
        if (t == 0) { g_pm[bid] = M; g_ps[bid] = stot; }
    }
}

// Weights-stationary node kernel: grid 32, block 256, 16 dsts/block.
// All stage weights staged into smem ONCE per block (112KB); per-dst data kept
// transposed [k][dst] (stride DP=20, float4-aligned, conflict-light). Thread
// (o = t&63, q = t>>6) owns outputs o for 4 dsts (c0 = q*4). Each stage is a
// batched matvec: inputs via broadcast LDS.128, weights via conflict-free LDS.
struct NodeSmem {
    float wUpd1[2 * H * H];   // updW1 [128][64]
    float wVal2[H * H];       // valW2 [64][64]
    float wUpd2[H * H];       // updW2 [64][64]
    float wT1[2 * H * H];     // nattW1 [128][64] (or decW1 [64][64] in first half)
    float wT2[H * H];         // nvalW1 [64][64]
    float agg [H * DP], hbuf[H * DP], tmp[H * DP];
    float hid [H * DP], rbuf[H * DP], hnb[H * DP];
    float mu[NDST], rstd[NDST];
};

__global__ void __launch_bounds__(256) node_kernel(
    const float* __restrict__ valW2, const float* __restrict__ valB2,
    const float* __restrict__ updW1, const float* __restrict__ updB1,
    const float* __restrict__ updW2, const float* __restrict__ updB2,
    const float* __restrict__ lng, const float* __restrict__ lnb,
    const float* __restrict__ nattW1, const float* __restrict__ nattB1,
    const float* __restrict__ nvalW1, const float* __restrict__ nvalB1,
    const float* __restrict__ decW1, const float* __restrict__ decB1,
    const float* __restrict__ decW2, const float* __restrict__ decB2,
    float* __restrict__ out, int rb, int last)
{
    extern __shared__ __align__(16) float sraw[];
    NodeSmem* sm = (NodeSmem*)sraw;
    const int t = threadIdx.x, o = t & 63, q = t >> 6;
    const int c0 = q * 4;                 // local dst column base
    const int dbase = blockIdx.x * NDST;
    const int wb = rb ^ 1;

    // ---- Stage weights into smem (once per block) ----
    for (int i = t; i < 2 * H * H; i += 256) sm->wUpd1[i] = updW1[i];
    for (int i = t; i < H * H; i += 256) { sm->wVal2[i] = valW2[i]; sm->wUpd2[i] = updW2[i]; }
    if (!last) {
        for (int i = t; i < 2 * H * H; i += 256) sm->wT1[i] = nattW1[i];
        for (int i = t; i < H * H; i += 256)     sm->wT2[i] = nvalW1[i];
    } else {
        for (int i = t; i < H * H; i += 256)     sm->wT1[i] = decW1[i];
    }

    // ---- Stage 0: combine halves -> agg, load h (transposed [o][dst]) ----
#pragma unroll
    for (int dd = 0; dd < 4; dd++) {
        int d = dbase + c0 + dd;
        float m0 = g_pm[2 * d], m1 = g_pm[2 * d + 1];
        float M = fmaxf(m0, m1);
        float sc0 = __expf(m0 - M), sc1 = __expf(m1 - M);
        float stot = g_ps[2 * d] * sc0 + g_ps[2 * d + 1] * sc1;
        float a = g_pacc[(2 * d) * H + o] * sc0 + g_pacc[(2 * d + 1) * H + o] * sc1;
        sm->agg[o * DP + c0 + dd] = a / stot;
        sm->hbuf[o * DP + c0 + dd] = g_h[d * H + o];
    }
    __syncthreads();

    // ---- Stage 1: tmp = val_b2 + agg @ val_w2 ----
    {
        float a0 = 0.f, a1 = 0.f, a2 = 0.f, a3 = 0.f;
#pragma unroll 8
        for (int k = 0; k < H; k++) {
            float4 in4 = *(const float4*)&sm->agg[k * DP + c0];
            float wv = sm->wVal2[k * H + o];
            a0 += in4.x * wv; a1 += in4.y * wv; a2 += in4.z * wv; a3 += in4.w * wv;
        }
        float b = valB2[o];
        *(float4*)&sm->tmp[o * DP + c0] = make_float4(b + a0, b + a1, b + a2, b + a3);
    }
    __syncthreads();

    // ---- Stage 2: hid = relu(upd_b1 + h @ W1a + tmp @ W1b) ----
    {
        float a0 = 0.f, a1 = 0.f, a2 = 0.f, a3 = 0.f;
#pragma unroll 8
        for (int k = 0; k < H; k++) {
            float4 in4 = *(const float4*)&sm->hbuf[k * DP + c0];
            float wv = sm->wUpd1[k * H + o];
            a0 += in4.x * wv; a1 += in4.y * wv; a2 += in4.z * wv; a3 += in4.w * wv;
        }
#pragma unroll 8
        for (int k = 0; k < H; k++) {
            float4 in4 = *(const float4*)&sm->tmp[k * DP + c0];
            float wv = sm->wUpd1[(H + k) * H + o];
            a0 += in4.x * wv; a1 += in4.y * wv; a2 += in4.z * wv; a3 += in4.w * wv;
        }
        float b = updB1[o];
        *(float4*)&sm->hid[o * DP + c0] = make_float4(
            fmaxf(b + a0, 0.f), fmaxf(b + a1, 0.f), fmaxf(b + a2, 0.f), fmaxf(b + a3, 0.f));
    }
    __syncthreads();

    // ---- Stage 3: r = upd_b2 + hid @ upd_w2 + h ----
    {
        float a0 = 0.f, a1 = 0.f, a2 = 0.f, a3 = 0.f;
#pragma unroll 8
        for (int k = 0; k < H; k++) {
            float4 in4 = *(const float4*)&sm->hid[k * DP + c0];
            float wv = sm->wUpd2[k * H + o];
            a0 += in4.x * wv; a1 += in4.y * wv; a2 += in4.z * wv; a3 += in4.w * wv;
        }
        float b = updB2[o];
        float4 hv = *(const float4*)&sm->hbuf[o * DP + c0];
        *(float4*)&sm->rbuf[o * DP + c0] = make_float4(
            b + a0 + hv.x, b + a1 + hv.y, b + a2 + hv.z, b + a3 + hv.w);
    }
    __syncthreads();

    // ---- Stage 4a: LayerNorm stats (one thread per dst, conflict-free) ----
    if (t < NDST) {
        float s1 = 0.f, s2 = 0.f;
#pragma unroll 8
        for (int oo = 0; oo < H; oo++) {
            float v = sm->rbuf[oo * DP + t];
            s1 += v; s2 += v * v;
        }
        float m = s1 * (1.0f / H);
        float var = s2 * (1.0f / H) - m * m;
        sm->mu[t] = m;
        sm->rstd[t] = rsqrtf(var + LN_EPS);
    }
    __syncthreads();

    // ---- Stage 4b: hn = g*(r-mu)*rstd + b; write g_h ----
    {
        float g = lng[o], bb = lnb[o];
        float4 rv = *(const float4*)&sm->rbuf[o * DP + c0];
        float h0 = g * (rv.x - sm->mu[c0 + 0]) * sm->rstd[c0 + 0] + bb;
        float h1 = g * (rv.y - sm->mu[c0 + 1]) * sm->rstd[c0 + 1] + bb;
        float h2 = g * (rv.z - sm->mu[c0 + 2]) * sm->rstd[c0 + 2] + bb;
        float h3 = g * (rv.w - sm->mu[c0 + 3]) * sm->rstd[c0 + 3] + bb;
        *(float4*)&sm->hnb[o * DP + c0] = make_float4(h0, h1, h2, h3);
        if (!last) {
            g_h[(dbase + c0 + 0) * H + o] = h0;
            g_h[(dbase + c0 + 1) * H + o] = h1;
            g_h[(dbase + c0 + 2) * H + o] = h2;
            g_h[(dbase + c0 + 3) * H + o] = h3;
        }
    }
    __syncthreads();

    if (!last) {
        // ---- Stage 5: next-layer tables (3 matvecs, 4 dsts per thread) ----
        float ad0 = 0.f, ad1 = 0.f, ad2 = 0.f, ad3 = 0.f;
        float as0 = 0.f, as1 = 0.f, as2 = 0.f, as3 = 0.f;
        float av0 = 0.f, av1 = 0.f, av2 = 0.f, av3 = 0.f;
#pragma unroll 4
        for (int k = 0; k < H; k++) {
            float4 hn4 = *(const float4*)&sm->hnb[k * DP + c0];
            float w1 = sm->wT1[k * H + o];
            float w2 = sm->wT1[(H + k) * H + o];
            float w3 = sm->wT2[k * H + o];
            ad0 += hn4.x * w1; ad1 += hn4.y * w1; ad2 += hn4.z * w1; ad3 += hn4.w * w1;
            as0 += hn4.x * w2; as1 += hn4.y * w2; as2 += hn4.z * w2; as3 += hn4.w * w2;
            av0 += hn4.x * w3; av1 += hn4.y * w3; av2 += hn4.z * w3; av3 += hn4.w * w3;
        }
        float ba = nattB1[o], bv = nvalB1[o];
        int d = dbase + c0;
        g_Hd[(d + 0) * H + o] = ad0 + ba;
        g_Hd[(d + 1) * H + o] = ad1 + ba;
        g_Hd[(d + 2) * H + o] = ad2 + ba;
        g_Hd[(d + 3) * H + o] = ad3 + ba;
        *(float4*)&g_HsT[wb][o * NN + d] = make_float4(as0, as1, as2, as3);
        g_Av[wb][(d + 0) * H + o] = av0 + bv;
        g_Av[wb][(d + 1) * H + o] = av1 + bv;
        g_Av[wb][(d + 2) * H + o] = av2 + bv;
        g_Av[wb][(d + 3) * H + o] = av3 + bv;
    } else {
        // ---- Decoder: hid2 = relu(decB1 + hn@decW1); out = decB2 + hid2 . decW2 ----
        float a0 = 0.f, a1 = 0.f, a2 = 0.f, a3 = 0.f;
#pragma unroll 8
        for (int k = 0; k < H; k++) {
            float4 hn4 = *(const float4*)&sm->hnb[k * DP + c0];
            float wv = sm->wT1[k * H + o];
            a0 += hn4.x * wv; a1 += hn4.y * wv; a2 += hn4.z * wv; a3 += hn4.w * wv;
        }
        float b = decB1[o];
        *(float4*)&sm->agg[o * DP + c0] = make_float4(
            fmaxf(b + a0, 0.f), fmaxf(b + a1, 0.f), fmaxf(b + a2, 0.f), fmaxf(b + a3, 0.f));
        __syncthreads();
        if (t < NDST) {
            float s = 0.f;
#pragma unroll 8
            for (int oo = 0; oo < H; oo++)
                s += sm->agg[oo * DP + t] * __ldg(decW2 + oo);
            out[dbase + t] = s + decB2[0];
        }
    }
}

extern "C" void kernel_launch(void* const* d_in, const int* in_sizes, int n_in,
                              void* d_out, int out_size)
{
    const float* x      = (const float*)d_in[0];
    const float* ea     = (const float*)d_in[1];
    const float* enc_w1 = (const float*)d_in[2];
    const float* enc_b1 = (const float*)d_in[3];
    const float* enc_w2 = (const float*)d_in[4];
    const float* enc_b2 = (const float*)d_in[5];
    const float* att_w1 = (const float*)d_in[6];   // [4,134,64]
    const float* att_b1 = (const float*)d_in[7];   // [4,64]
    const float* att_w2 = (const float*)d_in[8];   // [4,64,1]
    // d_in[9] = att_b2 — cancels inside softmax, unused
    const float* val_w1 = (const float*)d_in[10];  // [4,70,64]
    const float* val_b1 = (const float*)d_in[11];  // [4,64]
    const float* val_w2 = (const float*)d_in[12];  // [4,64,64]
    const float* val_b2 = (const float*)d_in[13];  // [4,64]
    const float* upd_w1 = (const float*)d_in[14];  // [4,128,64]
    const float* upd_b1 = (const float*)d_in[15];  // [4,64]
    const float* upd_w2 = (const float*)d_in[16];  // [4,64,64]
    const float* upd_b2 = (const float*)d_in[17];  // [4,64]
    const float* ln_g   = (const float*)d_in[18];  // [4,64]
    const float* ln_b   = (const float*)d_in[19];  // [4,64]
    const float* dec_w1 = (const float*)d_in[20];
    const float* dec_b1 = (const float*)d_in[21];
    const float* dec_w2 = (const float*)d_in[22];
    const float* dec_b2 = (const float*)d_in[23];
    // d_in[24] = edge_index: src=e/512, dst=e%512 (structure exploited directly)

    float* out = (float*)d_out;

    static_assert(sizeof(NodeSmem) < 200 * 1024, "node smem too big");
    cudaFuncSetAttribute(node_kernel, cudaFuncAttributeMaxDynamicSharedMemorySize,
                         (int)sizeof(NodeSmem));

    ea_transpose_kernel<<<dim3(16, 16), 256>>>(ea);
    enc_kernel<<<NN, H>>>(x, enc_w1, enc_b1, enc_w2, enc_b2,
                          att_w1, att_b1, val_w1, val_b1);

    for (int l = 0; l < NL; l++) {
        int last = (l == NL - 1);
        int nl = (l + 1) % NL;      // dummy-but-valid pointers on last layer
        int rb = l & 1;             // enc wrote buffer 0; layer l reads l&1, writes (l&1)^1
        edge_kernel<<<2 * NN, 128>>>(att_w1 + (l * 134 + 128) * H,
                                     att_w2 + l * H,
                                     val_w1 + (l * 70 + 64) * H,
                                     rb);
        node_kernel<<<NN / NDST, 256, sizeof(NodeSmem)>>>(
                                 val_w2 + l * H * H, val_b2 + l * H,
                                 upd_w1 + l * 2 * H * H, upd_b1 + l * H,
                                 upd_w2 + l * H * H, upd_b2 + l * H,
                                 ln_g + l * H, ln_b + l * H,
                                 att_w1 + nl * 134 * H, att_b1 + nl * H,
                                 val_w1 + nl * 70 * H, val_b1 + nl * H,
                                 dec_w1, dec_b1, dec_w2, dec_b2,
                                 out, rb, last);
    }
}

// round 14
// speedup vs baseline: 1.4604x; 1.4604x over previous
#include <cuda_runtime.h>

#define NN 512
#define H  64
#define ED 6
#define NL 4
#define EE (NN*NN)
#define LN_EPS 1e-5f

// Scratch (device globals: no allocations allowed)
__device__ float g_h  [NN*H];
__device__ float g_Hd [NN*H];         // dst-side attention proj (+att_b1), row-major
__device__ float g_HsT[2][H*NN];      // src-side attention proj, DIM-MAJOR [j][s], double buffered
__device__ float g_Av [2][NN*H];      // src-side value proj (+val_b1), row-major, double buffered
__device__ float g_eaT[ED*EE];        // edge_attr transposed: eaT[k][d][s]

__device__ __forceinline__ float warp_sum(float v) {
#pragma unroll
    for (int o = 16; o; o >>= 1) v += __shfl_xor_sync(0xffffffffu, v, o);
    return v;
}
__device__ __forceinline__ float warp_max(float v) {
#pragma unroll
    for (int o = 16; o; o >>= 1) v = fmaxf(v, __shfl_xor_sync(0xffffffffu, v, o));
    return v;
}

// Per-node tables: Hd = h@Wa[0:64]+b1a (row), HsT = h@Wa[64:128] (dim-major), Av = h@Wv[0:64]+b1v (row)
__device__ __forceinline__ void compute_tables(
    int d, int t, int wb, const float* h_sh,
    const float* __restrict__ attW1, const float* __restrict__ attB1,
    const float* __restrict__ valW1, const float* __restrict__ valB1)
{
    float ad = attB1[t], as = 0.f, av = valB1[t];
#pragma unroll 8
    for (int k = 0; k < H; k++) {
        float hk = h_sh[k];
        ad += hk * attW1[k * H + t];
        as += hk * attW1[(H + k) * H + t];
        av += hk * valW1[k * H + t];
    }
    g_Hd[d * H + t]       = ad;
    g_HsT[wb][t * NN + d] = as;
    g_Av[wb][d * H + t]   = av;
}

// Transpose edge_attr: ea[s][d][k] -> eaT[k][d][s]. grid (16,16), block 256.
__global__ void __launch_bounds__(256) ea_transpose_kernel(const float* __restrict__ ea)
{
    __shared__ float t_sh[ED][32][33];
    const int t = threadIdx.x, w = t >> 5, lane = t & 31;
    const int bs = blockIdx.x * 32, bd = blockIdx.y * 32;

#pragma unroll
    for (int rr = 0; rr < 4; rr++) {
        int s_loc = w + rr * 8;
        const float* base = ea + ((size_t)(bs + s_loc) * NN + bd) * ED + lane * ED;
        float2 v0 = *(const float2*)(base);
        float2 v1 = *(const float2*)(base + 2);
        float2 v2 = *(const float2*)(base + 4);
        t_sh[0][lane][s_loc] = v0.x; t_sh[1][lane][s_loc] = v0.y;
        t_sh[2][lane][s_loc] = v1.x; t_sh[3][lane][s_loc] = v1.y;
        t_sh[4][lane][s_loc] = v2.x; t_sh[5][lane][s_loc] = v2.y;
    }
    __syncthreads();
#pragma unroll
    for (int idx = t; idx < ED * 32 * 32; idx += 256) {
        int k = idx >> 10, r = idx & 1023, dl = r >> 5, sl = r & 31;
        g_eaT[(size_t)k * EE + (size_t)(bd + dl) * NN + bs + sl] = t_sh[k][dl][sl];
    }
}

// Encoder: h = relu(x@W1+b1)@W2+b2, then layer-0 tables (buffer 0). grid=512, block=64
__global__ void __launch_bounds__(H) enc_kernel(
    const float* __restrict__ x,
    const float* __restrict__ ew1, const float* __restrict__ eb1,
    const float* __restrict__ ew2, const float* __restrict__ eb2,
    const float* __restrict__ attW1, const float* __restrict__ attB1,
    const float* __restrict__ valW1, const float* __restrict__ valB1)
{
    int d = blockIdx.x, t = threadIdx.x;
    __shared__ float xs[ED], hid[H], hsn[H];
    if (t < ED) xs[t] = x[d * ED + t];
    __syncthreads();
    float a = eb1[t];
#pragma unroll
    for (int k = 0; k < ED; k++) a += xs[k] * ew1[k * H + t];
    hid[t] = fmaxf(a, 0.f);
    __syncthreads();
    float hv = eb2[t];
#pragma unroll 8
    for (int k = 0; k < H; k++) hv += hid[k] * ew2[k * H + t];
    g_h[d * H + t] = hv;
    hsn[t] = hv;
    __syncthreads();
    compute_tables(d, t, 0, hsn, attW1, attB1, valW1, valB1);
}

// Per-src logit term: leaky_relu(hd + hs + ea@We, 0.2). Balanced FMA tree,
// two independent sub-chains for ILP. Caller accumulates lg = fmaf(z, wo, lg).
__device__ __forceinline__ float logit_z(
    float hdhs, float e0, float e1, float e2, float e3, float e4, float e5,
    float4 wa, float4 wb)
{
    float a = fmaf(e0, wa.x, hdhs);
    float b = fmaf(e2, wa.z, e1 * wa.y);
    float c = fmaf(e4, wb.x, e3 * wa.w);
    float d = e5 * wb.y;
    float z = (a + b) + (c + d);
    return fmaxf(z, 0.2f * z);
}

// Fused layer (R6 champion structure, scalar inner loops): one block per dst d.
// 128 threads = 4 warps; warp w owns srcs [w*128, w*128+128); lane owns 4 srcs.
// All 512 blocks co-resident -> single wave. No inline asm: compiler-scheduled
// scalar FFMA trees (no f32x2 memcpy/MOV overhead, no scheduling barriers).
__global__ void __launch_bounds__(128, 5) layer_kernel(
    const float* __restrict__ attW1e,   // [6,64] edge rows of att_w1[l]
    const float* __restrict__ attW2,    // [64]
    const float* __restrict__ valW1e,   // [6,64] edge rows of val_w1[l]
    const float* __restrict__ valW2, const float* __restrict__ valB2,
    const float* __restrict__ updW1, const float* __restrict__ updB1,
    const float* __restrict__ updW2, const float* __restrict__ updB2,
    const float* __restrict__ lng, const float* __restrict__ lnb,
    const float* __restrict__ nattW1, const float* __restrict__ nattB1,
    const float* __restrict__ nvalW1, const float* __restrict__ nvalB1,
    const float* __restrict__ decW1, const float* __restrict__ decB1,
    const float* __restrict__ decW2, const float* __restrict__ decB2,
    float* __restrict__ out, int rb, int last)
{
    const int d = blockIdx.x;
    const int t = threadIdx.x, w = t >> 5, lane = t & 31;
    const int wb = rb ^ 1;

    __shared__ __align__(16) float4 waA[H];      // per j: (w0,w1,w2,w3)
    __shared__ __align__(16) float4 waB[H];      // per j: (w4,w5,wo,hd)
    __shared__ __align__(16) float4 ea_sh[NN*2]; // per s: (e0,e1,e2,e3),(e4,e5,-,-)
    __shared__ float  wexp[NN];                  // per s: softmax weight
    __shared__ float  pm[4], ps[4], pacc[4 * H];
    __shared__ float  part2[2 * H], agg_sh[H], h_sh[H], tmp_sh[H], hid_sh[H], hn_sh[H], red_sh[4];

    // Prologue: weight table + Hd row
    if (t < H) {
        int j = t;
        waA[j] = make_float4(attW1e[0 * H + j], attW1e[1 * H + j],
                             attW1e[2 * H + j], attW1e[3 * H + j]);
        waB[j] = make_float4(attW1e[4 * H + j], attW1e[5 * H + j],
                             attW2[j], g_Hd[d * H + j]);
    }

    const float* HsT = g_HsT[rb];
    const float* AvL = g_Av[rb];
    const int sa = w * 128 + 4 * lane;   // 4 srcs: sa..sa+3

    // Load ea for the 4 srcs (float4 from eaT, contiguous) — registers
    float4 eaq[ED];
#pragma unroll
    for (int k = 0; k < ED; k++)
        eaq[k] = *(const float4*)(g_eaT + (size_t)k * EE + d * NN + sa);

    // Publish ea for pass 2: [s][8] padded layout, 2 float4 per src
    ea_sh[(sa + 0) * 2 + 0] = make_float4(eaq[0].x, eaq[1].x, eaq[2].x, eaq[3].x);
    ea_sh[(sa + 0) * 2 + 1] = make_float4(eaq[4].x, eaq[5].x, 0.f, 0.f);
    ea_sh[(sa + 1) * 2 + 0] = make_float4(eaq[0].y, eaq[1].y, eaq[2].y, eaq[3].y);
    ea_sh[(sa + 1) * 2 + 1] = make_float4(eaq[4].y, eaq[5].y, 0.f, 0.f);
    ea_sh[(sa + 2) * 2 + 0] = make_float4(eaq[0].z, eaq[1].z, eaq[2].z, eaq[3].z);
    ea_sh[(sa + 2) * 2 + 1] = make_float4(eaq[4].z, eaq[5].z, 0.f, 0.f);
    ea_sh[(sa + 3) * 2 + 0] = make_float4(eaq[0].w, eaq[1].w, eaq[2].w, eaq[3].w);
    ea_sh[(sa + 3) * 2 + 1] = make_float4(eaq[4].w, eaq[5].w, 0.f, 0.f);
    __syncthreads();

    // ---- Pass 1: attention logits for the 4 srcs, full j-loop (scalar) ----
    float lg0 = 0.f, lg1 = 0.f, lg2 = 0.f, lg3 = 0.f;
#pragma unroll 8
    for (int j = 0; j < H; j++) {
        float4 wa = waA[j];
        float4 wbv = waB[j];
        float4 hs4 = *(const float4*)(HsT + j * NN + sa);
        float hd = wbv.w, wo = wbv.z;
        float z0 = logit_z(hd + hs4.x, eaq[0].x, eaq[1].x, eaq[2].x, eaq[3].x, eaq[4].x, eaq[5].x, wa, wbv);
        float z1 = logit_z(hd + hs4.y, eaq[0].y, eaq[1].y, eaq[2].y, eaq[3].y, eaq[4].y, eaq[5].y, wa, wbv);
        float z2 = logit_z(hd + hs4.z, eaq[0].z, eaq[1].z, eaq[2].z, eaq[3].z, eaq[4].z, eaq[5].z, wa, wbv);
        float z3 = logit_z(hd + hs4.w, eaq[0].w, eaq[1].w, eaq[2].w, eaq[3].w, eaq[4].w, eaq[5].w, wa, wbv);
        lg0 = fmaf(z0, wo, lg0);
        lg1 = fmaf(z1, wo, lg1);
        lg2 = fmaf(z2, wo, lg2);
        lg3 = fmaf(z3, wo, lg3);
    }

    // ---- Per-warp register softmax over this warp's 128 srcs ----
    {
        float m = warp_max(fmaxf(fmaxf(lg0, lg1), fmaxf(lg2, lg3)));
        float e0 = __expf(lg0 - m), e1 = __expf(lg1 - m);
        float e2 = __expf(lg2 - m), e3 = __expf(lg3 - m);
        float s_w = warp_sum(e0 + e1 + e2 + e3);
        if (lane == 0) { pm[w] = m; ps[w] = s_w; }
        *(float4*)(wexp + sa) = make_float4(e0, e1, e2, e3);
    }
    __syncthreads();

    // ---- Pass 2: alpha-weighted value aggregation (scalar, 2 dims/lane) ----
    const int j0 = 2 * lane;
    float wv0x = valW1e[0 * H + j0], wv0y = valW1e[0 * H + j0 + 1];
    float wv1x = valW1e[1 * H + j0], wv1y = valW1e[1 * H + j0 + 1];
    float wv2x = valW1e[2 * H + j0], wv2y = valW1e[2 * H + j0 + 1];
    float wv3x = valW1e[3 * H + j0], wv3y = valW1e[3 * H + j0 + 1];
    float wv4x = valW1e[4 * H + j0], wv4y = valW1e[4 * H + j0 + 1];
    float wv5x = valW1e[5 * H + j0], wv5y = valW1e[5 * H + j0 + 1];

    float acc0 = 0.f, acc1 = 0.f;
    const int s0 = w * 128;
    const float* avbase = AvL + j0;
#pragma unroll 4
    for (int i = 0; i < 128; i++) {
        int s = s0 + i;
        float al = wexp[s];
        float4 eA = ea_sh[s * 2 + 0];
        float4 eB = ea_sh[s * 2 + 1];
        float2 av = *(const float2*)(avbase + (size_t)s * H);
        // dim 0: two independent chains
        float p0a = fmaf(eA.x, wv0x, av.x);
        float p0b = eA.y * wv1x;
        p0a = fmaf(eA.z, wv2x, p0a);
        p0b = fmaf(eA.w, wv3x, p0b);
        p0a = fmaf(eB.x, wv4x, p0a);
        p0b = fmaf(eB.y, wv5x, p0b);
        float p0 = fmaxf(p0a + p0b, 0.f);
        // dim 1
        float p1a = fmaf(eA.x, wv0y, av.y);
        float p1b = eA.y * wv1y;
        p1a = fmaf(eA.z, wv2y, p1a);
        p1b = fmaf(eA.w, wv3y, p1b);
        p1a = fmaf(eB.x, wv4y, p1a);
        p1b = fmaf(eB.y, wv5y, p1b);
        float p1 = fmaxf(p1a + p1b, 0.f);
        acc0 = fmaf(al, p0, acc0);
        acc1 = fmaf(al, p1, acc1);
    }
    pacc[w * H + j0]     = acc0;
    pacc[w * H + j0 + 1] = acc1;
    __syncthreads();

    // ---- Combine 4 warp softmax partials ----
    if (t < H) {
        float M = fmaxf(fmaxf(pm[0], pm[1]), fmaxf(pm[2], pm[3]));
        float sc0 = __expf(pm[0] - M), sc1 = __expf(pm[1] - M);
        float sc2 = __expf(pm[2] - M), sc3 = __expf(pm[3] - M);
        float stot = ps[0] * sc0 + ps[1] * sc1 + ps[2] * sc2 + ps[3] * sc3;
        float a = pacc[0 * H + t] * sc0 + pacc[1 * H + t] * sc1
                + pacc[2 * H + t] * sc2 + pacc[3 * H + t] * sc3;
        agg_sh[t] = a / stot;
        h_sh[t]   = g_h[d * H + t];
    }
    __syncthreads();

    // ---- Node phase, 2-way k-split matvecs over 128 threads ----
    const int o = t & 63, q = t >> 6;

    // stage 1: tmp = val_b2 + agg @ val_w2
    {
        float p = 0.f;
        int k0 = q * 32;
#pragma unroll
        for (int kk = 0; kk < 32; kk++) p += agg_sh[k0 + kk] * valW2[(k0 + kk) * H + o];
        part2[q * H + o] = p;
    }
    __syncthreads();
    if (t < H) tmp_sh[t] = valB2[t] + part2[t] + part2[H + t];
    __syncthreads();

    // stage 2: hid = relu(upd_b1 + [h,tmp] @ upd_w1)
    {
        const float* srcv = (q == 0) ? h_sh : tmp_sh;
        int rbase = q * H;
        float p = 0.f;
#pragma unroll
        for (int kk = 0; kk < 64; kk++) p += srcv[kk] * updW1[(rbase + kk) * H + o];
        part2[q * H + o] = p;
    }
    __syncthreads();
    if (t < H) hid_sh[t] = fmaxf(updB1[t] + part2[t] + part2[H + t], 0.f);
    __syncthreads();

    // stage 3: u = upd_b2 + hid @ upd_w2
    {
        float p = 0.f;
        int k0 = q * 32;
#pragma unroll
        for (int kk = 0; kk < 32; kk++) p += hid_sh[k0 + kk] * updW2[(k0 + kk) * H + o];
        part2[q * H + o] = p;
    }
    __syncthreads();

    // residual + LayerNorm (threads 0..63 = warps 0,1; fused sum/sumsq)
    float r = 0.f, dr = 0.f;
    if (t < H) {
        float u = updB2[t] + part2[t] + part2[H + t];
        r = u + h_sh[t];
        float s1 = warp_sum(r);
        float s2 = warp_sum(r * r);
        if (lane == 0) { red_sh[w] = s1; red_sh[w + 2] = s2; }
    }
    __syncthreads();
    if (t < H) {
        float mu  = (red_sh[0] + red_sh[1]) * (1.0f / H);
        float ex2 = (red_sh[2] + red_sh[3]) * (1.0f / H);
        float var = ex2 - mu * mu;
        dr = r - mu;
        float hn = lng[t] * dr * rsqrtf(var + LN_EPS) + lnb[t];
        hn_sh[t] = hn;
        if (!last) g_h[d * H + t] = hn;
    }
    __syncthreads();

    if (!last) {
        if (t < H)
            compute_tables(d, t, wb, hn_sh, nattW1, nattB1, nvalW1, nvalB1);
    } else {
        if (t < H) {
            float dh = decB1[t];
#pragma unroll 8
            for (int k = 0; k < H; k++) dh += hn_sh[k] * decW1[k * H + t];
            dh = fmaxf(dh, 0.f);
            float p = dh * decW2[t];
            float psum = warp_sum(p);
            if (lane == 0) red_sh[w] = psum;
        }
        __syncthreads();
        if (t == 0) out[d] = red_sh[0] + red_sh[1] + decB2[0];
    }
}

extern "C" void kernel_launch(void* const* d_in, const int* in_sizes, int n_in,
                              void* d_out, int out_size)
{
    const float* x      = (const float*)d_in[0];
    const float* ea     = (const float*)d_in[1];
    const float* enc_w1 = (const float*)d_in[2];
    const float* enc_b1 = (const float*)d_in[3];
    const float* enc_w2 = (const float*)d_in[4];
    const float* enc_b2 = (const float*)d_in[5];
    const float* att_w1 = (const float*)d_in[6];   // [4,134,64]
    const float* att_b1 = (const float*)d_in[7];   // [4,64]
    const float* att_w2 = (const float*)d_in[8];   // [4,64,1]
    // d_in[9] = att_b2 — cancels inside softmax, unused
    const float* val_w1 = (const float*)d_in[10];  // [4,70,64]
    const float* val_b1 = (const float*)d_in[11];  // [4,64]
    const float* val_w2 = (const float*)d_in[12];  // [4,64,64]
    const float* val_b2 = (const float*)d_in[13];  // [4,64]
    const float* upd_w1 = (const float*)d_in[14];  // [4,128,64]
    const float* upd_b1 = (const float*)d_in[15];  // [4,64]
    const float* upd_w2 = (const float*)d_in[16];  // [4,64,64]
    const float* upd_b2 = (const float*)d_in[17];  // [4,64]
    const float* ln_g   = (const float*)d_in[18];  // [4,64]
    const float* ln_b   = (const float*)d_in[19];  // [4,64]
    const float* dec_w1 = (const float*)d_in[20];
    const float* dec_b1 = (const float*)d_in[21];
    const float* dec_w2 = (const float*)d_in[22];
    const float* dec_b2 = (const float*)d_in[23];
    // d_in[24] = edge_index: src=e/512, dst=e%512 (structure exploited directly)

    float* out = (float*)d_out;

    ea_transpose_kernel<<<dim3(16, 16), 256>>>(ea);
    enc_kernel<<<NN, H>>>(x, enc_w1, enc_b1, enc_w2, enc_b2,
                          att_w1, att_b1, val_w1, val_b1);

    for (int l = 0; l < NL; l++) {
        int last = (l == NL - 1);
        int nl = (l + 1) % NL;      // dummy-but-valid pointers on last layer
        int rb = l & 1;             // enc wrote buffer 0; layer l reads l&1, writes (l&1)^1
        layer_kernel<<<NN, 128>>>(att_w1 + (l * 134 + 128) * H,
                                  att_w2 + l * H,
                                  val_w1 + (l * 70 + 64) * H,
                                  val_w2 + l * H * H, val_b2 + l * H,
                                  upd_w1 + l * 2 * H * H, upd_b1 + l * H,
                                  upd_w2 + l * H * H, upd_b2 + l * H,
                                  ln_g + l * H, ln_b + l * H,
                                  att_w1 + nl * 134 * H, att_b1 + nl * H,
                                  val_w1 + nl * 70 * H, val_b1 + nl * H,
                                  dec_w1, dec_b1, dec_w2, dec_b2,
                                  out, rb, last);
    }
}